// round 2
// baseline (speedup 1.0000x reference)
#include <cuda_runtime.h>
#include <stdint.h>

// Problem constants (shape (32, 1024, 2048), mask fraction 0.25 -> k=512)
#define D        2048
#define KSEL     512
#define THREADS  256
#define VPT      (D / THREADS)   // 8 elements per thread

__global__ __launch_bounds__(THREADS, 8)
void obs_mask_kernel(const float* __restrict__ data,
                     const float* __restrict__ noise,
                     const float* __restrict__ randv,
                     float* __restrict__ out_masked,
                     float* __restrict__ out_inv)
{
    __shared__ uint32_t s_bits[D];        // rand row as raw bits (monotonic: all >= 0)
    __shared__ uint32_t s_hist[256];
    __shared__ uint8_t  s_mask[D];        // 0 = keep, 1 = masked, 2 = equal-to-threshold (temp)
    __shared__ uint32_t s_cnt[THREADS];
    __shared__ uint32_t s_wsum[8];
    __shared__ uint32_t s_sel[2];         // [0]=digit, [1]=remaining-after

    const int t    = threadIdx.x;
    const int lane = t & 31;
    const long long base = (long long)blockIdx.x * D;

    // ---- Phase 1: load rand row into smem (coalesced float4) ----
    {
        const float4* r4 = (const float4*)(randv + base);
        #pragma unroll
        for (int v = 0; v < 2; v++) {
            int vi = t + v * THREADS;          // 0..511 float4s
            float4 x = r4[vi];
            int i = vi * 4;
            s_bits[i + 0] = __float_as_uint(x.x);
            s_bits[i + 1] = __float_as_uint(x.y);
            s_bits[i + 2] = __float_as_uint(x.z);
            s_bits[i + 3] = __float_as_uint(x.w);
        }
    }
    __syncthreads();

    // ---- Phase 2: radix select (4 passes of 8 bits, from MSB) ----
    uint32_t prefHi    = 0;     // known high bits of the k-th largest
    uint32_t remaining = KSEL;  // rank still to place among active elements

    #pragma unroll
    for (int shift = 24; shift >= 0; shift -= 8) {
        s_hist[t] = 0;
        __syncthreads();

        #pragma unroll
        for (int j = 0; j < VPT; j++) {
            uint32_t b = s_bits[t * VPT + j];
            bool active = (shift == 24) ||
                          ((b >> (shift + 8)) == (prefHi >> (shift + 8)));
            uint32_t digit = (b >> shift) & 0xFFu;
            uint32_t key = active ? digit : 0x100u;
            unsigned peers = __match_any_sync(0xFFFFFFFFu, key);
            if (active) {
                int leader = __ffs(peers) - 1;
                if (lane == leader)
                    atomicAdd(&s_hist[digit], (uint32_t)__popc(peers));
            }
        }
        __syncthreads();

        // one warp picks the digit: largest d with count(>d) < remaining <= count(>=d)
        if (t < 32) {
            uint32_t local[8];
            uint32_t lsum = 0;
            #pragma unroll
            for (int j = 0; j < 8; j++) { local[j] = s_hist[t * 8 + j]; lsum += local[j]; }
            // inclusive suffix-sum across lanes (sum over lanes >= t)
            uint32_t x = lsum;
            #pragma unroll
            for (int off = 1; off < 32; off <<= 1) {
                uint32_t y = __shfl_down_sync(0xFFFFFFFFu, x, off);
                if (t + off < 32) x += y;
            }
            uint32_t c = x - lsum;       // count of elements with digit >= (t+1)*8
            int   found = -1;
            uint32_t remAfter = 0;
            for (int j = 7; j >= 0; j--) {
                uint32_t nc = c + local[j];
                if (found < 0 && c < remaining && remaining <= nc) {
                    found = t * 8 + j;
                    remAfter = remaining - c;
                }
                c = nc;
            }
            if (found >= 0) { s_sel[0] = (uint32_t)found; s_sel[1] = remAfter; }
        }
        __syncthreads();
        prefHi   |= s_sel[0] << shift;
        remaining = s_sel[1];
        __syncthreads();   // protect s_sel / s_hist before next pass rewrites
    }

    const uint32_t T       = prefHi;     // exact bit pattern of the 512th-largest
    const uint32_t need_eq = remaining;  // how many equals (lowest index first) get masked

    // ---- Phase 3: mark >T, and tie-break ==T by index (jax top_k semantics) ----
    {
        uint32_t cnt = 0;
        #pragma unroll
        for (int j = 0; j < VPT; j++) {
            uint32_t b = s_bits[t * VPT + j];
            uint8_t m = (b > T) ? 1 : ((b == T) ? 2 : 0);
            s_mask[t * VPT + j] = m;
            cnt += (m == 2);
        }
        s_cnt[t] = cnt;
        __syncthreads();

        // exclusive prefix over 256 per-thread equal-counts
        int wid = t >> 5;
        uint32_t v = s_cnt[t];
        uint32_t sc = v;
        #pragma unroll
        for (int off = 1; off < 32; off <<= 1) {
            uint32_t y = __shfl_up_sync(0xFFFFFFFFu, sc, off);
            if (lane >= off) sc += y;
        }
        if (lane == 31) s_wsum[wid] = sc;
        __syncthreads();
        uint32_t wbase = 0;
        for (int w = 0; w < wid; w++) wbase += s_wsum[w];
        uint32_t r = wbase + sc - v;     // exclusive rank among equals, in index order

        #pragma unroll
        for (int j = 0; j < VPT; j++) {
            int i = t * VPT + j;
            if (s_mask[i] == 2) {
                s_mask[i] = (r < need_eq) ? 1 : 0;
                r++;
            }
        }
        __syncthreads();
    }

    // ---- Phase 4: stream data/noise, apply mask, write both outputs ----
    {
        const float4* d4 = (const float4*)(data  + base);
        const float4* n4 = (const float4*)(noise + base);
        float4* oA = (float4*)(out_masked + base);
        float4* oB = (float4*)(out_inv    + base);
        #pragma unroll
        for (int v = 0; v < 2; v++) {
            int vi = t + v * THREADS;
            float4 dd = d4[vi];
            float4 nn = n4[vi];
            int i = vi * 4;
            float4 m, inv;
            bool k0 = s_mask[i + 0] != 0;
            bool k1 = s_mask[i + 1] != 0;
            bool k2 = s_mask[i + 2] != 0;
            bool k3 = s_mask[i + 3] != 0;
            m.x = k0 ? 0.0f : fmaf(0.1f, nn.x, dd.x);
            m.y = k1 ? 0.0f : fmaf(0.1f, nn.y, dd.y);
            m.z = k2 ? 0.0f : fmaf(0.1f, nn.z, dd.z);
            m.w = k3 ? 0.0f : fmaf(0.1f, nn.w, dd.w);
            inv.x = k0 ? 0.0f : 1.0f;
            inv.y = k1 ? 0.0f : 1.0f;
            inv.z = k2 ? 0.0f : 1.0f;
            inv.w = k3 ? 0.0f : 1.0f;
            oA[vi] = m;
            oB[vi] = inv;
        }
    }
}

extern "C" void kernel_launch(void* const* d_in, const int* in_sizes, int n_in,
                              void* d_out, int out_size)
{
    const float* data  = (const float*)d_in[0];
    const float* noise = (const float*)d_in[1];
    const float* randv = (const float*)d_in[2];
    float* out = (float*)d_out;

    long long N = (long long)in_sizes[0];     // 32*1024*2048 = 67108864
    int rows = (int)(N / D);                  // 32768

    float* out_masked = out;
    float* out_inv    = out + N;              // outputs concatenated: (masked, mask_inverse)

    obs_mask_kernel<<<rows, THREADS>>>(data, noise, randv, out_masked, out_inv);
}

// round 7
// speedup vs baseline: 1.2695x; 1.2695x over previous
#include <cuda_runtime.h>
#include <stdint.h>

#define D        2048
#define KSEL     512
#define THREADS  256

__global__ __launch_bounds__(THREADS, 6)
void obs_mask_kernel(const float* __restrict__ data,
                     const float* __restrict__ noise,
                     const float* __restrict__ randv,
                     float* __restrict__ out_masked,
                     float* __restrict__ out_inv)
{
    __shared__ uint32_t s_hist[256];
    __shared__ uint32_t s_wsum[8];
    __shared__ uint32_t s_sel[2];     // [0]=digit, [1]=remaining-after
    __shared__ uint32_t s_lotot;

    const int t    = threadIdx.x;
    const int lane = t & 31;
    const int wid  = t >> 5;
    const long long base = (long long)blockIdx.x * D;

    // ---- Phase 1: rand row -> 8 registers (two coalesced float4s) ----
    uint32_t b[8];
    {
        const float4* r4 = (const float4*)(randv + base);
        float4 r0 = r4[t];          // elements 4t .. 4t+3
        float4 r1 = r4[t + 256];    // elements 1024+4t .. 1024+4t+3
        b[0] = __float_as_uint(r0.x); b[1] = __float_as_uint(r0.y);
        b[2] = __float_as_uint(r0.z); b[3] = __float_as_uint(r0.w);
        b[4] = __float_as_uint(r1.x); b[5] = __float_as_uint(r1.y);
        b[6] = __float_as_uint(r1.z); b[7] = __float_as_uint(r1.w);
    }

    // ---- Phase 2: radix select, 4 passes of 8 bits, values stay in registers ----
    uint32_t prefHi    = 0;
    uint32_t remaining = KSEL;

    #pragma unroll
    for (int shift = 24; shift >= 0; shift -= 8) {
        s_hist[t] = 0;
        __syncthreads();

        #pragma unroll
        for (int j = 0; j < 8; j++) {
            bool active = (shift == 24) ||
                          ((b[j] >> (shift + 8)) == (prefHi >> (shift + 8)));
            uint32_t digit = (b[j] >> shift) & 0xFFu;
            uint32_t key = active ? digit : 0x100u;
            unsigned peers = __match_any_sync(0xFFFFFFFFu, key);
            if (active && lane == (__ffs(peers) - 1))
                atomicAdd(&s_hist[digit], (uint32_t)__popc(peers));
        }
        __syncthreads();

        // one warp picks: largest digit d with count(>d) < remaining <= count(>=d)
        if (t < 32) {
            uint32_t local[8];
            uint32_t lsum = 0;
            #pragma unroll
            for (int j = 0; j < 8; j++) { local[j] = s_hist[t * 8 + j]; lsum += local[j]; }
            uint32_t x = lsum;   // inclusive suffix-sum over lanes >= t
            #pragma unroll
            for (int off = 1; off < 32; off <<= 1) {
                uint32_t y = __shfl_down_sync(0xFFFFFFFFu, x, off);
                if (t + off < 32) x += y;
            }
            uint32_t c = x - lsum;    // count with digit >= (t+1)*8
            int found = -1; uint32_t remAfter = 0;
            for (int j = 7; j >= 0; j--) {
                uint32_t nc = c + local[j];
                if (found < 0 && c < remaining && remaining <= nc) {
                    found = t * 8 + j;
                    remAfter = remaining - c;
                }
                c = nc;
            }
            if (found >= 0) { s_sel[0] = (uint32_t)found; s_sel[1] = remAfter; }
        }
        __syncthreads();
        prefHi   |= s_sel[0] << shift;
        remaining = s_sel[1];
        __syncthreads();   // protect s_sel/s_hist before next pass
    }

    const uint32_t T       = prefHi;
    const uint32_t need_eq = remaining;

    // ---- Phase 3: register mask + exact tie-break in GLOBAL index order ----
    // thread t owns: lo indices 4t+j (j=0..3), hi indices 1024+4t+j (j=4..7)
    uint32_t mk = 0, eqm = 0;
    uint32_t cnt_lo = 0, cnt_hi = 0;
    #pragma unroll
    for (int j = 0; j < 8; j++) {
        bool gt = b[j] > T;
        bool eq = b[j] == T;
        if (gt) mk  |= 1u << j;
        if (eq) eqm |= 1u << j;
        if (eq) { if (j < 4) cnt_lo++; else cnt_hi++; }
    }

    {
        // pack (lo,hi) counts; exclusive block scan in thread order gives
        // index-order prefixes within each half
        uint32_t v  = cnt_lo | (cnt_hi << 16);
        uint32_t sc = v;
        #pragma unroll
        for (int off = 1; off < 32; off <<= 1) {
            uint32_t y = __shfl_up_sync(0xFFFFFFFFu, sc, off);
            if (lane >= off) sc += y;
        }
        if (lane == 31) s_wsum[wid] = sc;
        __syncthreads();
        uint32_t wbase = 0;
        #pragma unroll
        for (int w = 0; w < 8; w++) if (w < wid) wbase += s_wsum[w];
        if (t == THREADS - 1) s_lotot = (wbase + sc) & 0xFFFFu;  // total lo equals
        uint32_t ex = wbase + sc - v;                            // exclusive prefix
        __syncthreads();
        uint32_t r_lo = ex & 0xFFFFu;
        uint32_t r_hi = s_lotot + (ex >> 16);

        #pragma unroll
        for (int j = 0; j < 4; j++) {
            if (eqm & (1u << j)) { if (r_lo < need_eq) mk |= 1u << j; r_lo++; }
        }
        #pragma unroll
        for (int j = 4; j < 8; j++) {
            if (eqm & (1u << j)) { if (r_hi < need_eq) mk |= 1u << j; r_hi++; }
        }
    }

    // ---- Phase 4: stream data/noise, apply register mask, write both outputs ----
    {
        const float4* d4 = (const float4*)(data  + base);
        const float4* n4 = (const float4*)(noise + base);
        float4* oA = (float4*)(out_masked + base);
        float4* oB = (float4*)(out_inv    + base);
        #pragma unroll
        for (int v = 0; v < 2; v++) {
            int vi = (v == 0) ? t : (t + 256);
            float4 dd = d4[vi];
            float4 nn = n4[vi];
            int jb = v * 4;
            bool k0 = (mk >> (jb + 0)) & 1u;
            bool k1 = (mk >> (jb + 1)) & 1u;
            bool k2 = (mk >> (jb + 2)) & 1u;
            bool k3 = (mk >> (jb + 3)) & 1u;
            float4 m, inv;
            m.x = k0 ? 0.0f : fmaf(0.1f, nn.x, dd.x);
            m.y = k1 ? 0.0f : fmaf(0.1f, nn.y, dd.y);
            m.z = k2 ? 0.0f : fmaf(0.1f, nn.z, dd.z);
            m.w = k3 ? 0.0f : fmaf(0.1f, nn.w, dd.w);
            inv.x = k0 ? 0.0f : 1.0f;
            inv.y = k1 ? 0.0f : 1.0f;
            inv.z = k2 ? 0.0f : 1.0f;
            inv.w = k3 ? 0.0f : 1.0f;
            oA[vi] = m;
            oB[vi] = inv;
        }
    }
}

extern "C" void kernel_launch(void* const* d_in, const int* in_sizes, int n_in,
                              void* d_out, int out_size)
{
    const float* data  = (const float*)d_in[0];
    const float* noise = (const float*)d_in[1];
    const float* randv = (const float*)d_in[2];
    float* out = (float*)d_out;

    long long N = (long long)in_sizes[0];     // 67108864
    int rows = (int)(N / D);                  // 32768

    obs_mask_kernel<<<rows, THREADS>>>(data, noise, randv, out, out + N);
}